// round 5
// baseline (speedup 1.0000x reference)
#include <cuda_runtime.h>
#include <cuda_bf16.h>
#include <cstddef>

// Problem constants
#define BATCH 2
#define LEN   1024
#define DM    1024
#define DI    2048
#define NST   16
#define KCONV 4
#define RRANK 64
#define XDBL_W 96   // R + 2N

// ---------------- scratch (static device arrays; no allocation) -------------
__device__ __align__(256) float g_xz[BATCH * LEN * 2 * DI];    // (2048, 4096)
__device__ __align__(256) float g_xconv[BATCH * LEN * DI];     // (2048, 2048)
__device__ __align__(256) float g_xdbl[BATCH * LEN * XDBL_W];  // (2048, 96)
__device__ __align__(256) float g_xdbl_part[8 * BATCH * LEN * XDBL_W]; // split-K partials
__device__ __align__(256) float g_dt[BATCH * LEN * DI];        // (2048, 2048)
__device__ __align__(256) float g_y[BATCH * LEN * DI];         // (2048, 2048)

// ============================================================================
// TF32 tensor-core GEMM: C(M,N) = A(M,K) @ B(K,N), all row-major.
// Double-buffered smem, 1 sync per k-tile. NO occupancy bound: ptxas keeps
// ~170 regs, zero spills, 1 CTA/SM (8 warps).
// Requires M%128==0, N%128==0, K%16==0. ACT: 0 = none, 1 = bias + softplus
// ============================================================================
#define TBM 128
#define TBN 128
#define TBK 16
#define SA  20    // As row stride in words (pad 16->20: conflict-free frag loads)
#define SB  136   // Bs row stride in words (pad 128->136: conflict-free)

__device__ __forceinline__ unsigned f2tf32(float f) {
    unsigned r;
    asm("cvt.rna.tf32.f32 %0, %1;" : "=r"(r) : "f"(f));
    return r;
}

__device__ __forceinline__ void mma_tf32(float c[4],
                                         unsigned a0, unsigned a1, unsigned a2, unsigned a3,
                                         unsigned b0, unsigned b1) {
    asm volatile(
        "mma.sync.aligned.m16n8k8.row.col.f32.tf32.tf32.f32 "
        "{%0,%1,%2,%3}, {%4,%5,%6,%7}, {%8,%9}, {%0,%1,%2,%3};"
        : "+f"(c[0]), "+f"(c[1]), "+f"(c[2]), "+f"(c[3])
        : "r"(a0), "r"(a1), "r"(a2), "r"(a3), "r"(b0), "r"(b1));
}

template <int ACT>
__global__ __launch_bounds__(256) void tf32_gemm(
    int M, int N, int K,
    const float* __restrict__ A, int lda,
    const float* __restrict__ B, int ldb,
    float* __restrict__ C, int ldc,
    const float* __restrict__ bias)
{
    __shared__ unsigned As[2][TBM * SA];   // 2 x 10240 B
    __shared__ unsigned Bs[2][TBK * SB];   // 2 x 8704 B

    const int tid  = threadIdx.x;
    const int wid  = tid >> 5;
    const int lane = tid & 31;
    const int g    = lane >> 2;   // group id (0..7)
    const int tig  = lane & 3;    // thread in group (0..3)
    const int bm   = blockIdx.y * TBM;
    const int bn   = blockIdx.x * TBN;
    const int wm   = (wid >> 2) * 64;   // warp m offset (0 or 64)
    const int wn   = (wid & 3) * 32;    // warp n offset (0..96)

    float acc[4][4][4];
#pragma unroll
    for (int mt = 0; mt < 4; mt++)
#pragma unroll
        for (int nt = 0; nt < 4; nt++)
#pragma unroll
            for (int i = 0; i < 4; i++) acc[mt][nt][i] = 0.f;

    // Global load mapping
    const int ar = tid >> 2;          // A row (0..63), also +64
    const int ac = (tid & 3) * 4;     // A col (float4)
    const int bk = tid >> 5;          // B row (0..7), also +8
    const int bc = (tid & 31) * 4;    // B col (float4)

    const float* Ap0 = A + (size_t)(bm + ar) * lda + ac;
    const float* Ap1 = A + (size_t)(bm + ar + 64) * lda + ac;
    const float* Bp0 = B + (size_t)bk * ldb + bn + bc;
    const float* Bp1 = B + (size_t)(bk + 8) * ldb + bn + bc;

    float4 a0r, a1r, b0r, b1r;

#define LOADG(K0)                                                     \
    do {                                                              \
        a0r = *(const float4*)(Ap0 + (K0));                           \
        a1r = *(const float4*)(Ap1 + (K0));                           \
        b0r = *(const float4*)(Bp0 + (size_t)(K0) * ldb);             \
        b1r = *(const float4*)(Bp1 + (size_t)(K0) * ldb);             \
    } while (0)

#define STORES(BUF)                                                   \
    do {                                                              \
        unsigned* ap = &As[BUF][ar * SA + ac];                        \
        ap[0] = f2tf32(a0r.x); ap[1] = f2tf32(a0r.y);                 \
        ap[2] = f2tf32(a0r.z); ap[3] = f2tf32(a0r.w);                 \
        unsigned* ap2 = &As[BUF][(ar + 64) * SA + ac];                \
        ap2[0] = f2tf32(a1r.x); ap2[1] = f2tf32(a1r.y);               \
        ap2[2] = f2tf32(a1r.z); ap2[3] = f2tf32(a1r.w);               \
        unsigned* bp = &Bs[BUF][bk * SB + bc];                        \
        bp[0] = f2tf32(b0r.x); bp[1] = f2tf32(b0r.y);                 \
        bp[2] = f2tf32(b0r.z); bp[3] = f2tf32(b0r.w);                 \
        unsigned* bp2 = &Bs[BUF][(bk + 8) * SB + bc];                 \
        bp2[0] = f2tf32(b1r.x); bp2[1] = f2tf32(b1r.y);               \
        bp2[2] = f2tf32(b1r.z); bp2[3] = f2tf32(b1r.w);               \
    } while (0)

#define COMPUTE(BUF)                                                           \
    do {                                                                       \
        _Pragma("unroll")                                                      \
        for (int kk = 0; kk < TBK; kk += 8) {                                  \
            unsigned bf[4][2];                                                 \
            _Pragma("unroll")                                                  \
            for (int nt = 0; nt < 4; nt++) {                                   \
                bf[nt][0] = Bs[BUF][(kk + tig) * SB + wn + nt * 8 + g];        \
                bf[nt][1] = Bs[BUF][(kk + tig + 4) * SB + wn + nt * 8 + g];    \
            }                                                                  \
            _Pragma("unroll")                                                  \
            for (int mt = 0; mt < 4; mt++) {                                   \
                int row = wm + mt * 16 + g;                                    \
                unsigned a0 = As[BUF][row * SA + kk + tig];                    \
                unsigned a1 = As[BUF][(row + 8) * SA + kk + tig];              \
                unsigned a2 = As[BUF][row * SA + kk + tig + 4];                \
                unsigned a3 = As[BUF][(row + 8) * SA + kk + tig + 4];          \
                _Pragma("unroll")                                              \
                for (int nt = 0; nt < 4; nt++)                                 \
                    mma_tf32(acc[mt][nt], a0, a1, a2, a3, bf[nt][0], bf[nt][1]);\
            }                                                                  \
        }                                                                      \
    } while (0)

    const int nk = K / TBK;

    // Prologue: fill buffer 0, stage LDGs for tile 1
    LOADG(0);
    STORES(0);
    if (nk > 1) LOADG(TBK);
    __syncthreads();

    for (int kt = 0; kt < nk; kt++) {
        const int cur = kt & 1;
        COMPUTE(cur);
        if (kt + 1 < nk) {
            STORES(cur ^ 1);                  // staged regs -> other buffer
            if (kt + 2 < nk) LOADG((kt + 2) * TBK);  // prefetch next-next
            __syncthreads();
        }
    }

    // Epilogue
#pragma unroll
    for (int mt = 0; mt < 4; mt++) {
#pragma unroll
        for (int nt = 0; nt < 4; nt++) {
            int r0 = bm + wm + mt * 16 + g;
            int c0 = bn + wn + nt * 8 + tig * 2;
            float v0 = acc[mt][nt][0], v1 = acc[mt][nt][1];
            float v2 = acc[mt][nt][2], v3 = acc[mt][nt][3];
            if (ACT == 1) {
                v0 += bias[c0];     v1 += bias[c0 + 1];
                v2 += bias[c0];     v3 += bias[c0 + 1];
                v0 = (v0 > 20.f) ? v0 : log1pf(__expf(v0));
                v1 = (v1 > 20.f) ? v1 : log1pf(__expf(v1));
                v2 = (v2 > 20.f) ? v2 : log1pf(__expf(v2));
                v3 = (v3 > 20.f) ? v3 : log1pf(__expf(v3));
            }
            float2 p01 = make_float2(v0, v1);
            float2 p23 = make_float2(v2, v3);
            *(float2*)&C[(size_t)r0 * ldc + c0] = p01;
            *(float2*)&C[(size_t)(r0 + 8) * ldc + c0] = p23;
        }
    }
#undef LOADG
#undef STORES
#undef COMPUTE
}

// ============================================================================
// GEMM2 (x_dbl = x_conv @ W_x), N=96, K=2048: split-K fp32, partials + reduce
// ============================================================================
#define G2_BM 64
#define G2_BK 16
#define G2_KS 8     // K splits
#define G2_KC (DI / G2_KS)  // 256 per split

__global__ __launch_bounds__(256) void gemm2_partial(const float* __restrict__ Wx)
{
    __shared__ float As2[G2_BK][G2_BM + 1];   // +1 pad: distinct banks for STS
    __shared__ float Bs2[G2_BK][XDBL_W];
    const int tid = threadIdx.x;
    const int tx = tid & 15;   // 16 col-threads -> 6 cols each
    const int ty = tid >> 4;   // 16 row-threads -> 4 rows each
    const int ks = blockIdx.x;
    const int bm = blockIdx.y * G2_BM;
    const int kbeg = ks * G2_KC;

    float acc[4][6];
#pragma unroll
    for (int i = 0; i < 4; i++)
#pragma unroll
        for (int j = 0; j < 6; j++) acc[i][j] = 0.f;

    for (int k0 = kbeg; k0 < kbeg + G2_KC; k0 += G2_BK) {
#pragma unroll
        for (int i = tid; i < G2_BM * G2_BK; i += 256) {
            int m = i >> 4, k = i & 15;
            As2[k][m] = g_xconv[(size_t)(bm + m) * DI + k0 + k];
        }
#pragma unroll
        for (int i = tid; i < G2_BK * XDBL_W; i += 256) {
            int k = i / XDBL_W, n = i % XDBL_W;
            Bs2[k][n] = Wx[(size_t)(k0 + k) * XDBL_W + n];
        }
        __syncthreads();
#pragma unroll
        for (int k = 0; k < G2_BK; k++) {
            float a[4], b[6];
#pragma unroll
            for (int i = 0; i < 4; i++) a[i] = As2[k][ty * 4 + i];
#pragma unroll
            for (int j = 0; j < 6; j++) b[j] = Bs2[k][tx * 6 + j];
#pragma unroll
            for (int i = 0; i < 4; i++)
#pragma unroll
                for (int j = 0; j < 6; j++)
                    acc[i][j] = fmaf(a[i], b[j], acc[i][j]);
        }
        __syncthreads();
    }
#pragma unroll
    for (int i = 0; i < 4; i++)
#pragma unroll
        for (int j = 0; j < 6; j++)
            g_xdbl_part[((size_t)ks * (BATCH * LEN) + bm + ty * 4 + i) * XDBL_W
                        + tx * 6 + j] = acc[i][j];
}

__global__ void xdbl_reduce_kernel()
{
    int i = blockIdx.x * blockDim.x + threadIdx.x;
    if (i >= BATCH * LEN * XDBL_W) return;
    float s = 0.f;
#pragma unroll
    for (int p = 0; p < G2_KS; p++)
        s += g_xdbl_part[(size_t)p * (BATCH * LEN * XDBL_W) + i];
    g_xdbl[i] = s;
}

// ---------------- causal depthwise conv1d + SiLU ----------------------------
__global__ void conv_silu_kernel(const float* __restrict__ conv_w,
                                 const float* __restrict__ conv_b)
{
    int idx = blockIdx.x * blockDim.x + threadIdx.x; // over B*L*DI
    if (idx >= BATCH * LEN * DI) return;
    int d = idx & (DI - 1);
    int l = (idx >> 11) & (LEN - 1);
    int b = idx >> 21;
    float acc = conv_b[d];
#pragma unroll
    for (int j = 0; j < KCONV; j++) {
        int ll = l - (KCONV - 1) + j;
        if (ll >= 0)
            acc = fmaf(conv_w[d * KCONV + j],
                       g_xz[((size_t)(b * LEN + ll)) * (2 * DI) + d], acc);
    }
    acc = acc / (1.f + __expf(-acc)); // SiLU
    g_xconv[idx] = acc;
}

// ---------------- conv cache output -----------------------------------------
__global__ void conv_cache_kernel(float* __restrict__ cc)
{
    int idx = blockIdx.x * blockDim.x + threadIdx.x; // B*DI*K
    if (idx >= BATCH * DI * KCONV) return;
    int j = idx & (KCONV - 1);
    int d = (idx >> 2) & (DI - 1);
    int b = idx >> 13;
    cc[idx] = g_xz[((size_t)(b * LEN + (LEN - KCONV + j))) * (2 * DI) + d];
}

// ---------------- selective scan (sequential over L) ------------------------
__global__ __launch_bounds__(256) void scan_kernel(
    const float* __restrict__ A_log,
    const float* __restrict__ D_param,
    float* __restrict__ h_final)
{
    const int tid = threadIdx.x;
    const int gc = blockIdx.x * 16 + (tid >> 4); // global channel 0..4095
    const int n = tid & 15;
    const int b = gc >> 11;
    const int d = gc & (DI - 1);

    const float Acoef = -__expf(A_log[d * NST + n]);
    const float Dv = D_param[d];
    float h = 0.f;

    const size_t base = (size_t)b * LEN;
    float dt_c = g_dt[base * DI + d];
    float u_c  = g_xconv[base * DI + d];
    float B_c  = g_xdbl[base * XDBL_W + RRANK + n];
    float C_c  = g_xdbl[base * XDBL_W + RRANK + NST + n];

    for (int l = 0; l < LEN; l++) {
        float dt_n = 0.f, u_n = 0.f, B_n = 0.f, C_n = 0.f;
        if (l + 1 < LEN) {
            size_t r = base + l + 1;
            dt_n = g_dt[r * DI + d];
            u_n  = g_xconv[r * DI + d];
            B_n  = g_xdbl[r * XDBL_W + RRANK + n];
            C_n  = g_xdbl[r * XDBL_W + RRANK + NST + n];
        }
        float abar = __expf(dt_c * Acoef);
        h = fmaf(abar, h, dt_c * B_c * u_c);
        float v = h * C_c;
#pragma unroll
        for (int off = 8; off; off >>= 1)
            v += __shfl_xor_sync(0xffffffffu, v, off);
        if (n == 0) {
            size_t r = base + l;
            float zv = g_xz[r * (2 * DI) + DI + d];
            float sil = zv / (1.f + __expf(-zv));
            g_y[r * DI + d] = (v + Dv * u_c) * sil;
        }
        dt_c = dt_n; u_c = u_n; B_c = B_n; C_c = C_n;
    }
    h_final[((size_t)b * DI + d) * NST + n] = h;
}

// ---------------- launch -----------------------------------------------------
extern "C" void kernel_launch(void* const* d_in, const int* in_sizes, int n_in,
                              void* d_out, int out_size)
{
    const float* x       = (const float*)d_in[0];
    const float* W_in    = (const float*)d_in[1];
    const float* conv_w  = (const float*)d_in[2];
    const float* conv_b  = (const float*)d_in[3];
    const float* W_x     = (const float*)d_in[4];
    const float* W_dt    = (const float*)d_in[5];
    const float* b_dt    = (const float*)d_in[6];
    const float* A_log   = (const float*)d_in[7];
    const float* D_param = (const float*)d_in[8];
    const float* W_out   = (const float*)d_in[9];

    float* out_f = (float*)d_out;
    float* out_main  = out_f;                                   // (2,1024,1024)
    float* out_hfin  = out_f + BATCH * LEN * DM;                // (2,2048,16)
    float* out_cache = out_hfin + BATCH * DI * NST;             // (2,2048,4)

    float *xz, *xdbl, *dt, *y;
    cudaGetSymbolAddress((void**)&xz, g_xz);
    cudaGetSymbolAddress((void**)&xdbl, g_xdbl);
    cudaGetSymbolAddress((void**)&dt, g_dt);
    cudaGetSymbolAddress((void**)&y, g_y);

    const int M = BATCH * LEN; // 2048

    // 1) xz = x @ W_in   (2048 x 4096 x 1024)  [tf32 TC]
    {
        dim3 grid((2 * DI) / TBN, M / TBM);
        tf32_gemm<0><<<grid, 256>>>(M, 2 * DI, DM, x, DM, W_in, 2 * DI,
                                    xz, 2 * DI, nullptr);
    }
    // 2) conv + silu
    {
        int tot = BATCH * LEN * DI;
        conv_silu_kernel<<<(tot + 255) / 256, 256>>>(conv_w, conv_b);
    }
    // 3) conv cache output
    {
        int tot = BATCH * DI * KCONV;
        conv_cache_kernel<<<(tot + 255) / 256, 256>>>(out_cache);
    }
    // 4) x_dbl = x_conv @ W_x   (2048 x 96 x 2048)  [split-K fp32]
    {
        dim3 grid(G2_KS, M / G2_BM);  // (8, 32)
        gemm2_partial<<<grid, 256>>>(W_x);
        int tot = BATCH * LEN * XDBL_W;
        xdbl_reduce_kernel<<<(tot + 255) / 256, 256>>>();
    }
    // 5) dt = softplus(dt_low @ W_dt + b_dt)   (2048 x 2048 x 64)  [tf32 TC]
    {
        dim3 grid(DI / TBN, M / TBM);
        tf32_gemm<1><<<grid, 256>>>(M, DI, RRANK, xdbl, XDBL_W, W_dt, DI,
                                    dt, DI, b_dt);
    }
    // 6) selective scan (fused D-skip + silu(z) gate) -> g_y, h_final
    {
        scan_kernel<<<(BATCH * DI) / 16, 256>>>(A_log, D_param, out_hfin);
    }
    // 7) out = y @ W_out   (2048 x 1024 x 2048)  [tf32 TC]
    {
        dim3 grid(DM / TBN, M / TBM);
        tf32_gemm<0><<<grid, 256>>>(M, DM, DI, y, DI, W_out, DM,
                                    out_main, DM, nullptr);
    }
}

// round 6
// speedup vs baseline: 1.0798x; 1.0798x over previous
#include <cuda_runtime.h>
#include <cuda_fp16.h>
#include <cstddef>

// Problem constants
#define BATCH 2
#define LEN   1024
#define DM    1024
#define DI    2048
#define NST   16
#define KCONV 4
#define RRANK 64
#define XDBL_W 96   // R + 2N

// ---------------- scratch (static device arrays; no allocation) -------------
__device__ __align__(256) float g_xz[BATCH * LEN * 2 * DI];    // (2048, 4096)
__device__ __align__(256) float g_xconv[BATCH * LEN * DI];     // (2048, 2048)
__device__ __align__(256) float g_xdbl[BATCH * LEN * XDBL_W];  // (2048, 96)
__device__ __align__(256) float g_xdbl_part[8 * BATCH * LEN * XDBL_W]; // split-K partials
__device__ __align__(256) float g_dt[BATCH * LEN * DI];        // (2048, 2048)
__device__ __align__(256) float g_y[BATCH * LEN * DI];         // (2048, 2048)

// ============================================================================
// FP16 tensor-core GEMM (m16n8k16, fp32 accum): C(M,N) = A(M,K) @ B(K,N).
// All row-major fp32 in gmem; converted to half2 k-pairs in smem.
// Double-buffered, 1 sync/k-tile. Requires M%128==0, N%128==0, K%16==0.
// ACT: 0 = none, 1 = bias + softplus
// ============================================================================
#define TBM 128
#define TBN 128
#define TBK 16
#define SAH 36    // As row stride in half2 (8 data + pad): read banks 4g+tig distinct
#define SBH 136   // Bs row stride in half2: read banks 8*tig+g distinct

__device__ __forceinline__ unsigned packh2(float lo, float hi) {
    __half2 h = __floats2half2_rn(lo, hi);
    return *(unsigned*)&h;
}

__device__ __forceinline__ void mma_f16(float c[4],
                                        unsigned a0, unsigned a1, unsigned a2, unsigned a3,
                                        unsigned b0, unsigned b1) {
    asm volatile(
        "mma.sync.aligned.m16n8k16.row.col.f32.f16.f16.f32 "
        "{%0,%1,%2,%3}, {%4,%5,%6,%7}, {%8,%9}, {%0,%1,%2,%3};"
        : "+f"(c[0]), "+f"(c[1]), "+f"(c[2]), "+f"(c[3])
        : "r"(a0), "r"(a1), "r"(a2), "r"(a3), "r"(b0), "r"(b1));
}

template <int ACT>
__global__ __launch_bounds__(256) void fp16_gemm(
    int M, int N, int K,
    const float* __restrict__ A, int lda,
    const float* __restrict__ B, int ldb,
    float* __restrict__ C, int ldc,
    const float* __restrict__ bias)
{
    // As: 128 rows x 8 half2 (k-pairs), stride SAH.  Bs: 8 k-pairs x 128 n.
    __shared__ unsigned As[2][TBM * SAH];   // 2 x 18432 B
    __shared__ unsigned Bs[2][8 * SBH];     // 2 x  4352 B

    const int tid  = threadIdx.x;
    const int wid  = tid >> 5;
    const int lane = tid & 31;
    const int g    = lane >> 2;   // group id (0..7)
    const int tig  = lane & 3;    // thread in group (0..3)
    const int bm   = blockIdx.y * TBM;
    const int bn   = blockIdx.x * TBN;
    const int wm   = (wid >> 2) * 64;   // warp m offset (0 or 64)
    const int wn   = (wid & 3) * 32;    // warp n offset (0..96)

    float acc[4][4][4];
#pragma unroll
    for (int mt = 0; mt < 4; mt++)
#pragma unroll
        for (int nt = 0; nt < 4; nt++)
#pragma unroll
            for (int i = 0; i < 4; i++) acc[mt][nt][i] = 0.f;

    // Global load mapping.
    // A: thread -> row ar (and ar+64), float cols ac..ac+3 (one half2 pair x2)
    const int ar = tid >> 2;          // 0..63
    const int ac = (tid & 3) * 4;     // 0,4,8,12
    // B: warp w handles k-rows 2w and 2w+1, lane covers 4 consecutive n.
    const int bk = tid >> 5;          // 0..7
    const int bc = (tid & 31) * 4;    // 0..124

    const float* Ap0 = A + (size_t)(bm + ar) * lda + ac;
    const float* Ap1 = A + (size_t)(bm + ar + 64) * lda + ac;
    const float* Bp0 = B + (size_t)(2 * bk) * ldb + bn + bc;
    const float* Bp1 = B + (size_t)(2 * bk + 1) * ldb + bn + bc;

    float4 a0r, a1r, b0r, b1r;

#define LOADG(K0)                                                     \
    do {                                                              \
        a0r = *(const float4*)(Ap0 + (K0));                           \
        a1r = *(const float4*)(Ap1 + (K0));                           \
        b0r = *(const float4*)(Bp0 + (size_t)(K0) * ldb);             \
        b1r = *(const float4*)(Bp1 + (size_t)(K0) * ldb);             \
    } while (0)

#define STORES(BUF)                                                   \
    do {                                                              \
        uint2 av0 = make_uint2(packh2(a0r.x, a0r.y), packh2(a0r.z, a0r.w)); \
        *(uint2*)&As[BUF][ar * SAH + (ac >> 1)] = av0;                \
        uint2 av1 = make_uint2(packh2(a1r.x, a1r.y), packh2(a1r.z, a1r.w)); \
        *(uint2*)&As[BUF][(ar + 64) * SAH + (ac >> 1)] = av1;         \
        uint4 bv = make_uint4(packh2(b0r.x, b1r.x), packh2(b0r.y, b1r.y), \
                              packh2(b0r.z, b1r.z), packh2(b0r.w, b1r.w)); \
        *(uint4*)&Bs[BUF][bk * SBH + bc] = bv;                        \
    } while (0)

#define COMPUTE(BUF)                                                           \
    do {                                                                       \
        unsigned bf[4][2];                                                     \
        _Pragma("unroll")                                                      \
        for (int nt = 0; nt < 4; nt++) {                                       \
            bf[nt][0] = Bs[BUF][tig * SBH + wn + nt * 8 + g];                  \
            bf[nt][1] = Bs[BUF][(tig + 4) * SBH + wn + nt * 8 + g];            \
        }                                                                      \
        _Pragma("unroll")                                                      \
        for (int mt = 0; mt < 4; mt++) {                                       \
            int row = wm + mt * 16 + g;                                        \
            unsigned a0 = As[BUF][row * SAH + tig];                            \
            unsigned a1 = As[BUF][(row + 8) * SAH + tig];                      \
            unsigned a2 = As[BUF][row * SAH + tig + 4];                        \
            unsigned a3 = As[BUF][(row + 8) * SAH + tig + 4];                  \
            _Pragma("unroll")                                                  \
            for (int nt = 0; nt < 4; nt++)                                     \
                mma_f16(acc[mt][nt], a0, a1, a2, a3, bf[nt][0], bf[nt][1]);    \
        }                                                                      \
    } while (0)

    const int nk = K / TBK;

    // Prologue: fill buffer 0, stage LDGs for tile 1
    LOADG(0);
    STORES(0);
    if (nk > 1) LOADG(TBK);
    __syncthreads();

    for (int kt = 0; kt < nk; kt++) {
        const int cur = kt & 1;
        COMPUTE(cur);
        if (kt + 1 < nk) {
            STORES(cur ^ 1);                  // staged regs -> other buffer
            if (kt + 2 < nk) LOADG((kt + 2) * TBK);  // prefetch next-next
            __syncthreads();
        }
    }

    // Epilogue (C fragment: rows g/g+8, cols 2*tig, 2*tig+1 per 16x8 tile)
#pragma unroll
    for (int mt = 0; mt < 4; mt++) {
#pragma unroll
        for (int nt = 0; nt < 4; nt++) {
            int r0 = bm + wm + mt * 16 + g;
            int c0 = bn + wn + nt * 8 + tig * 2;
            float v0 = acc[mt][nt][0], v1 = acc[mt][nt][1];
            float v2 = acc[mt][nt][2], v3 = acc[mt][nt][3];
            if (ACT == 1) {
                v0 += bias[c0];     v1 += bias[c0 + 1];
                v2 += bias[c0];     v3 += bias[c0 + 1];
                v0 = (v0 > 20.f) ? v0 : log1pf(__expf(v0));
                v1 = (v1 > 20.f) ? v1 : log1pf(__expf(v1));
                v2 = (v2 > 20.f) ? v2 : log1pf(__expf(v2));
                v3 = (v3 > 20.f) ? v3 : log1pf(__expf(v3));
            }
            float2 p01 = make_float2(v0, v1);
            float2 p23 = make_float2(v2, v3);
            *(float2*)&C[(size_t)r0 * ldc + c0] = p01;
            *(float2*)&C[(size_t)(r0 + 8) * ldc + c0] = p23;
        }
    }
#undef LOADG
#undef STORES
#undef COMPUTE
}

// ============================================================================
// GEMM2 (x_dbl = x_conv @ W_x), N=96, K=2048: split-K fp32, partials + reduce
// ============================================================================
#define G2_BM 64
#define G2_BK 16
#define G2_KS 8     // K splits
#define G2_KC (DI / G2_KS)  // 256 per split

__global__ __launch_bounds__(256) void gemm2_partial(const float* __restrict__ Wx)
{
    __shared__ float As2[G2_BK][G2_BM + 1];   // +1 pad: distinct banks for STS
    __shared__ float Bs2[G2_BK][XDBL_W];
    const int tid = threadIdx.x;
    const int tx = tid & 15;   // 16 col-threads -> 6 cols each
    const int ty = tid >> 4;   // 16 row-threads -> 4 rows each
    const int ks = blockIdx.x;
    const int bm = blockIdx.y * G2_BM;
    const int kbeg = ks * G2_KC;

    float acc[4][6];
#pragma unroll
    for (int i = 0; i < 4; i++)
#pragma unroll
        for (int j = 0; j < 6; j++) acc[i][j] = 0.f;

    for (int k0 = kbeg; k0 < kbeg + G2_KC; k0 += G2_BK) {
#pragma unroll
        for (int i = tid; i < G2_BM * G2_BK; i += 256) {
            int m = i >> 4, k = i & 15;
            As2[k][m] = g_xconv[(size_t)(bm + m) * DI + k0 + k];
        }
#pragma unroll
        for (int i = tid; i < G2_BK * XDBL_W; i += 256) {
            int k = i / XDBL_W, n = i % XDBL_W;
            Bs2[k][n] = Wx[(size_t)(k0 + k) * XDBL_W + n];
        }
        __syncthreads();
#pragma unroll
        for (int k = 0; k < G2_BK; k++) {
            float a[4], b[6];
#pragma unroll
            for (int i = 0; i < 4; i++) a[i] = As2[k][ty * 4 + i];
#pragma unroll
            for (int j = 0; j < 6; j++) b[j] = Bs2[k][tx * 6 + j];
#pragma unroll
            for (int i = 0; i < 4; i++)
#pragma unroll
                for (int j = 0; j < 6; j++)
                    acc[i][j] = fmaf(a[i], b[j], acc[i][j]);
        }
        __syncthreads();
    }
#pragma unroll
    for (int i = 0; i < 4; i++)
#pragma unroll
        for (int j = 0; j < 6; j++)
            g_xdbl_part[((size_t)ks * (BATCH * LEN) + bm + ty * 4 + i) * XDBL_W
                        + tx * 6 + j] = acc[i][j];
}

__global__ void xdbl_reduce_kernel()
{
    int i = blockIdx.x * blockDim.x + threadIdx.x;
    if (i >= BATCH * LEN * XDBL_W) return;
    float s = 0.f;
#pragma unroll
    for (int p = 0; p < G2_KS; p++)
        s += g_xdbl_part[(size_t)p * (BATCH * LEN * XDBL_W) + i];
    g_xdbl[i] = s;
}

// ---------------- causal depthwise conv1d + SiLU ----------------------------
__global__ void conv_silu_kernel(const float* __restrict__ conv_w,
                                 const float* __restrict__ conv_b)
{
    int idx = blockIdx.x * blockDim.x + threadIdx.x; // over B*L*DI
    if (idx >= BATCH * LEN * DI) return;
    int d = idx & (DI - 1);
    int l = (idx >> 11) & (LEN - 1);
    int b = idx >> 21;
    float acc = conv_b[d];
#pragma unroll
    for (int j = 0; j < KCONV; j++) {
        int ll = l - (KCONV - 1) + j;
        if (ll >= 0)
            acc = fmaf(conv_w[d * KCONV + j],
                       g_xz[((size_t)(b * LEN + ll)) * (2 * DI) + d], acc);
    }
    acc = acc / (1.f + __expf(-acc)); // SiLU
    g_xconv[idx] = acc;
}

// ---------------- conv cache output -----------------------------------------
__global__ void conv_cache_kernel(float* __restrict__ cc)
{
    int idx = blockIdx.x * blockDim.x + threadIdx.x; // B*DI*K
    if (idx >= BATCH * DI * KCONV) return;
    int j = idx & (KCONV - 1);
    int d = (idx >> 2) & (DI - 1);
    int b = idx >> 13;
    cc[idx] = g_xz[((size_t)(b * LEN + (LEN - KCONV + j))) * (2 * DI) + d];
}

// ---------------- selective scan (sequential over L) ------------------------
__global__ __launch_bounds__(256) void scan_kernel(
    const float* __restrict__ A_log,
    const float* __restrict__ D_param,
    float* __restrict__ h_final)
{
    const int tid = threadIdx.x;
    const int gc = blockIdx.x * 16 + (tid >> 4); // global channel 0..4095
    const int n = tid & 15;
    const int b = gc >> 11;
    const int d = gc & (DI - 1);

    const float Acoef = -__expf(A_log[d * NST + n]);
    const float Dv = D_param[d];
    float h = 0.f;

    const size_t base = (size_t)b * LEN;
    float dt_c = g_dt[base * DI + d];
    float u_c  = g_xconv[base * DI + d];
    float B_c  = g_xdbl[base * XDBL_W + RRANK + n];
    float C_c  = g_xdbl[base * XDBL_W + RRANK + NST + n];

    for (int l = 0; l < LEN; l++) {
        float dt_n = 0.f, u_n = 0.f, B_n = 0.f, C_n = 0.f;
        if (l + 1 < LEN) {
            size_t r = base + l + 1;
            dt_n = g_dt[r * DI + d];
            u_n  = g_xconv[r * DI + d];
            B_n  = g_xdbl[r * XDBL_W + RRANK + n];
            C_n  = g_xdbl[r * XDBL_W + RRANK + NST + n];
        }
        float abar = __expf(dt_c * Acoef);
        h = fmaf(abar, h, dt_c * B_c * u_c);
        float v = h * C_c;
#pragma unroll
        for (int off = 8; off; off >>= 1)
            v += __shfl_xor_sync(0xffffffffu, v, off);
        if (n == 0) {
            size_t r = base + l;
            float zv = g_xz[r * (2 * DI) + DI + d];
            float sil = zv / (1.f + __expf(-zv));
            g_y[r * DI + d] = (v + Dv * u_c) * sil;
        }
        dt_c = dt_n; u_c = u_n; B_c = B_n; C_c = C_n;
    }
    h_final[((size_t)b * DI + d) * NST + n] = h;
}

// ---------------- launch -----------------------------------------------------
extern "C" void kernel_launch(void* const* d_in, const int* in_sizes, int n_in,
                              void* d_out, int out_size)
{
    const float* x       = (const float*)d_in[0];
    const float* W_in    = (const float*)d_in[1];
    const float* conv_w  = (const float*)d_in[2];
    const float* conv_b  = (const float*)d_in[3];
    const float* W_x     = (const float*)d_in[4];
    const float* W_dt    = (const float*)d_in[5];
    const float* b_dt    = (const float*)d_in[6];
    const float* A_log   = (const float*)d_in[7];
    const float* D_param = (const float*)d_in[8];
    const float* W_out   = (const float*)d_in[9];

    float* out_f = (float*)d_out;
    float* out_main  = out_f;                                   // (2,1024,1024)
    float* out_hfin  = out_f + BATCH * LEN * DM;                // (2,2048,16)
    float* out_cache = out_hfin + BATCH * DI * NST;             // (2,2048,4)

    float *xz, *xdbl, *dt, *y;
    cudaGetSymbolAddress((void**)&xz, g_xz);
    cudaGetSymbolAddress((void**)&xdbl, g_xdbl);
    cudaGetSymbolAddress((void**)&dt, g_dt);
    cudaGetSymbolAddress((void**)&y, g_y);

    const int M = BATCH * LEN; // 2048

    // 1) xz = x @ W_in   (2048 x 4096 x 1024)  [fp16 TC]
    {
        dim3 grid((2 * DI) / TBN, M / TBM);
        fp16_gemm<0><<<grid, 256>>>(M, 2 * DI, DM, x, DM, W_in, 2 * DI,
                                    xz, 2 * DI, nullptr);
    }
    // 2) conv + silu
    {
        int tot = BATCH * LEN * DI;
        conv_silu_kernel<<<(tot + 255) / 256, 256>>>(conv_w, conv_b);
    }
    // 3) conv cache output
    {
        int tot = BATCH * DI * KCONV;
        conv_cache_kernel<<<(tot + 255) / 256, 256>>>(out_cache);
    }
    // 4) x_dbl = x_conv @ W_x   (2048 x 96 x 2048)  [split-K fp32]
    {
        dim3 grid(G2_KS, M / G2_BM);  // (8, 32)
        gemm2_partial<<<grid, 256>>>(W_x);
        int tot = BATCH * LEN * XDBL_W;
        xdbl_reduce_kernel<<<(tot + 255) / 256, 256>>>();
    }
    // 5) dt = softplus(dt_low @ W_dt + b_dt)   (2048 x 2048 x 64)  [fp16 TC]
    {
        dim3 grid(DI / TBN, M / TBM);
        fp16_gemm<1><<<grid, 256>>>(M, DI, RRANK, xdbl, XDBL_W, W_dt, DI,
                                    dt, DI, b_dt);
    }
    // 6) selective scan (fused D-skip + silu(z) gate) -> g_y, h_final
    {
        scan_kernel<<<(BATCH * DI) / 16, 256>>>(A_log, D_param, out_hfin);
    }
    // 7) out = y @ W_out   (2048 x 1024 x 2048)  [fp16 TC]
    {
        dim3 grid(DM / TBN, M / TBM);
        fp16_gemm<0><<<grid, 256>>>(M, DM, DI, y, DI, W_out, DM,
                                    out_main, DM, nullptr);
    }
}

// round 7
// speedup vs baseline: 1.8006x; 1.6676x over previous
#include <cuda_runtime.h>
#include <cuda_fp16.h>
#include <cstddef>

// Problem constants
#define BATCH 2
#define LEN   1024
#define DM    1024
#define DI    2048
#define NST   16
#define KCONV 4
#define RRANK 64
#define XDBL_W 96   // R + 2N
#define NCH   16    // scan chunks
#define CHL   (LEN / NCH)   // 64 steps per chunk

// ---------------- scratch (static device arrays; no allocation) -------------
__device__ __align__(256) float g_xz[BATCH * LEN * 2 * DI];    // (2048, 4096)
__device__ __align__(256) float g_xconv[BATCH * LEN * DI];     // (2048, 2048)
__device__ __align__(256) float g_xdbl[BATCH * LEN * XDBL_W];  // (2048, 96)
__device__ __align__(256) float g_xdbl_part[8 * BATCH * LEN * XDBL_W];
__device__ __align__(256) float g_dt[BATCH * LEN * DI];        // (2048, 2048)
__device__ __align__(256) float g_y[BATCH * LEN * DI];         // (2048, 2048)
__device__ __align__(256) float g_aprod[BATCH * DI * NST * NCH];  // 4MB
__device__ __align__(256) float g_hend [BATCH * DI * NST * NCH];  // 4MB

// ============================================================================
// FP16 tensor-core GEMM (m16n8k16, fp32 accum): C(M,N) = A(M,K) @ B(K,N).
// ============================================================================
#define TBM 128
#define TBN 128
#define TBK 16
#define SAH 36
#define SBH 136

__device__ __forceinline__ unsigned packh2(float lo, float hi) {
    __half2 h = __floats2half2_rn(lo, hi);
    return *(unsigned*)&h;
}

__device__ __forceinline__ void mma_f16(float c[4],
                                        unsigned a0, unsigned a1, unsigned a2, unsigned a3,
                                        unsigned b0, unsigned b1) {
    asm volatile(
        "mma.sync.aligned.m16n8k16.row.col.f32.f16.f16.f32 "
        "{%0,%1,%2,%3}, {%4,%5,%6,%7}, {%8,%9}, {%0,%1,%2,%3};"
        : "+f"(c[0]), "+f"(c[1]), "+f"(c[2]), "+f"(c[3])
        : "r"(a0), "r"(a1), "r"(a2), "r"(a3), "r"(b0), "r"(b1));
}

template <int ACT>
__global__ __launch_bounds__(256) void fp16_gemm(
    int M, int N, int K,
    const float* __restrict__ A, int lda,
    const float* __restrict__ B, int ldb,
    float* __restrict__ C, int ldc,
    const float* __restrict__ bias)
{
    __shared__ unsigned As[2][TBM * SAH];
    __shared__ unsigned Bs[2][8 * SBH];

    const int tid  = threadIdx.x;
    const int wid  = tid >> 5;
    const int lane = tid & 31;
    const int g    = lane >> 2;
    const int tig  = lane & 3;
    const int bm   = blockIdx.y * TBM;
    const int bn   = blockIdx.x * TBN;
    const int wm   = (wid >> 2) * 64;
    const int wn   = (wid & 3) * 32;

    float acc[4][4][4];
#pragma unroll
    for (int mt = 0; mt < 4; mt++)
#pragma unroll
        for (int nt = 0; nt < 4; nt++)
#pragma unroll
            for (int i = 0; i < 4; i++) acc[mt][nt][i] = 0.f;

    const int ar = tid >> 2;
    const int ac = (tid & 3) * 4;
    const int bk = tid >> 5;
    const int bc = (tid & 31) * 4;

    const float* Ap0 = A + (size_t)(bm + ar) * lda + ac;
    const float* Ap1 = A + (size_t)(bm + ar + 64) * lda + ac;
    const float* Bp0 = B + (size_t)(2 * bk) * ldb + bn + bc;
    const float* Bp1 = B + (size_t)(2 * bk + 1) * ldb + bn + bc;

    float4 a0r, a1r, b0r, b1r;

#define LOADG(K0)                                                     \
    do {                                                              \
        a0r = *(const float4*)(Ap0 + (K0));                           \
        a1r = *(const float4*)(Ap1 + (K0));                           \
        b0r = *(const float4*)(Bp0 + (size_t)(K0) * ldb);             \
        b1r = *(const float4*)(Bp1 + (size_t)(K0) * ldb);             \
    } while (0)

#define STORES(BUF)                                                   \
    do {                                                              \
        uint2 av0 = make_uint2(packh2(a0r.x, a0r.y), packh2(a0r.z, a0r.w)); \
        *(uint2*)&As[BUF][ar * SAH + (ac >> 1)] = av0;                \
        uint2 av1 = make_uint2(packh2(a1r.x, a1r.y), packh2(a1r.z, a1r.w)); \
        *(uint2*)&As[BUF][(ar + 64) * SAH + (ac >> 1)] = av1;         \
        uint4 bv = make_uint4(packh2(b0r.x, b1r.x), packh2(b0r.y, b1r.y), \
                              packh2(b0r.z, b1r.z), packh2(b0r.w, b1r.w)); \
        *(uint4*)&Bs[BUF][bk * SBH + bc] = bv;                        \
    } while (0)

#define COMPUTE(BUF)                                                           \
    do {                                                                       \
        unsigned bf[4][2];                                                     \
        _Pragma("unroll")                                                      \
        for (int nt = 0; nt < 4; nt++) {                                       \
            bf[nt][0] = Bs[BUF][tig * SBH + wn + nt * 8 + g];                  \
            bf[nt][1] = Bs[BUF][(tig + 4) * SBH + wn + nt * 8 + g];            \
        }                                                                      \
        _Pragma("unroll")                                                      \
        for (int mt = 0; mt < 4; mt++) {                                       \
            int row = wm + mt * 16 + g;                                        \
            unsigned a0 = As[BUF][row * SAH + tig];                            \
            unsigned a1 = As[BUF][(row + 8) * SAH + tig];                      \
            unsigned a2 = As[BUF][row * SAH + tig + 4];                        \
            unsigned a3 = As[BUF][(row + 8) * SAH + tig + 4];                  \
            _Pragma("unroll")                                                  \
            for (int nt = 0; nt < 4; nt++)                                     \
                mma_f16(acc[mt][nt], a0, a1, a2, a3, bf[nt][0], bf[nt][1]);    \
        }                                                                      \
    } while (0)

    const int nk = K / TBK;

    LOADG(0);
    STORES(0);
    if (nk > 1) LOADG(TBK);
    __syncthreads();

    for (int kt = 0; kt < nk; kt++) {
        const int cur = kt & 1;
        COMPUTE(cur);
        if (kt + 1 < nk) {
            STORES(cur ^ 1);
            if (kt + 2 < nk) LOADG((kt + 2) * TBK);
            __syncthreads();
        }
    }

#pragma unroll
    for (int mt = 0; mt < 4; mt++) {
#pragma unroll
        for (int nt = 0; nt < 4; nt++) {
            int r0 = bm + wm + mt * 16 + g;
            int c0 = bn + wn + nt * 8 + tig * 2;
            float v0 = acc[mt][nt][0], v1 = acc[mt][nt][1];
            float v2 = acc[mt][nt][2], v3 = acc[mt][nt][3];
            if (ACT == 1) {
                v0 += bias[c0];     v1 += bias[c0 + 1];
                v2 += bias[c0];     v3 += bias[c0 + 1];
                v0 = (v0 > 20.f) ? v0 : log1pf(__expf(v0));
                v1 = (v1 > 20.f) ? v1 : log1pf(__expf(v1));
                v2 = (v2 > 20.f) ? v2 : log1pf(__expf(v2));
                v3 = (v3 > 20.f) ? v3 : log1pf(__expf(v3));
            }
            float2 p01 = make_float2(v0, v1);
            float2 p23 = make_float2(v2, v3);
            *(float2*)&C[(size_t)r0 * ldc + c0] = p01;
            *(float2*)&C[(size_t)(r0 + 8) * ldc + c0] = p23;
        }
    }
#undef LOADG
#undef STORES
#undef COMPUTE
}

// ============================================================================
// GEMM2 (x_dbl = x_conv @ W_x), N=96, K=2048: split-K fp32, partials + reduce
// ============================================================================
#define G2_BM 64
#define G2_BK 16
#define G2_KS 8
#define G2_KC (DI / G2_KS)

__global__ __launch_bounds__(256) void gemm2_partial(const float* __restrict__ Wx)
{
    __shared__ float As2[G2_BK][G2_BM + 1];
    __shared__ float Bs2[G2_BK][XDBL_W];
    const int tid = threadIdx.x;
    const int tx = tid & 15;
    const int ty = tid >> 4;
    const int ks = blockIdx.x;
    const int bm = blockIdx.y * G2_BM;
    const int kbeg = ks * G2_KC;

    float acc[4][6];
#pragma unroll
    for (int i = 0; i < 4; i++)
#pragma unroll
        for (int j = 0; j < 6; j++) acc[i][j] = 0.f;

    for (int k0 = kbeg; k0 < kbeg + G2_KC; k0 += G2_BK) {
#pragma unroll
        for (int i = tid; i < G2_BM * G2_BK; i += 256) {
            int m = i >> 4, k = i & 15;
            As2[k][m] = g_xconv[(size_t)(bm + m) * DI + k0 + k];
        }
#pragma unroll
        for (int i = tid; i < G2_BK * XDBL_W; i += 256) {
            int k = i / XDBL_W, n = i % XDBL_W;
            Bs2[k][n] = Wx[(size_t)(k0 + k) * XDBL_W + n];
        }
        __syncthreads();
#pragma unroll
        for (int k = 0; k < G2_BK; k++) {
            float a[4], b[6];
#pragma unroll
            for (int i = 0; i < 4; i++) a[i] = As2[k][ty * 4 + i];
#pragma unroll
            for (int j = 0; j < 6; j++) b[j] = Bs2[k][tx * 6 + j];
#pragma unroll
            for (int i = 0; i < 4; i++)
#pragma unroll
                for (int j = 0; j < 6; j++)
                    acc[i][j] = fmaf(a[i], b[j], acc[i][j]);
        }
        __syncthreads();
    }
#pragma unroll
    for (int i = 0; i < 4; i++)
#pragma unroll
        for (int j = 0; j < 6; j++)
            g_xdbl_part[((size_t)ks * (BATCH * LEN) + bm + ty * 4 + i) * XDBL_W
                        + tx * 6 + j] = acc[i][j];
}

__global__ void xdbl_reduce_kernel()
{
    int i = blockIdx.x * blockDim.x + threadIdx.x;
    if (i >= BATCH * LEN * XDBL_W) return;
    float s = 0.f;
#pragma unroll
    for (int p = 0; p < G2_KS; p++)
        s += g_xdbl_part[(size_t)p * (BATCH * LEN * XDBL_W) + i];
    g_xdbl[i] = s;
}

// ---------------- causal depthwise conv1d + SiLU ----------------------------
__global__ void conv_silu_kernel(const float* __restrict__ conv_w,
                                 const float* __restrict__ conv_b)
{
    int idx = blockIdx.x * blockDim.x + threadIdx.x;
    if (idx >= BATCH * LEN * DI) return;
    int d = idx & (DI - 1);
    int l = (idx >> 11) & (LEN - 1);
    int b = idx >> 21;
    float acc = conv_b[d];
#pragma unroll
    for (int j = 0; j < KCONV; j++) {
        int ll = l - (KCONV - 1) + j;
        if (ll >= 0)
            acc = fmaf(conv_w[d * KCONV + j],
                       g_xz[((size_t)(b * LEN + ll)) * (2 * DI) + d], acc);
    }
    acc = acc / (1.f + __expf(-acc));
    g_xconv[idx] = acc;
}

// ---------------- conv cache output -----------------------------------------
__global__ void conv_cache_kernel(float* __restrict__ cc)
{
    int idx = blockIdx.x * blockDim.x + threadIdx.x;
    if (idx >= BATCH * DI * KCONV) return;
    int j = idx & (KCONV - 1);
    int d = (idx >> 2) & (DI - 1);
    int b = idx >> 13;
    cc[idx] = g_xz[((size_t)(b * LEN + (LEN - KCONV + j))) * (2 * DI) + d];
}

// ============================================================================
// Chunked parallel selective scan.
// Thread = (channel gc, state n, chunk c).  16 lanes (n) per group, 16 groups
// per 256-thread block.  Pass 1: chunk summaries (prod a, h_end from h0=0).
// Pass 2: fold preceding summaries -> h_start, re-scan chunk, emit y/h_final.
// ============================================================================
__global__ __launch_bounds__(256) void scan_pass1(const float* __restrict__ A_log)
{
    const int tid = threadIdx.x;
    const int G  = blockIdx.x * 16 + (tid >> 4);  // (channel, chunk)
    const int c  = G & (NCH - 1);
    const int gc = G >> 4;                        // 0..4095 = b*DI + d
    const int n  = tid & 15;
    const int b  = gc >> 11;
    const int d  = gc & (DI - 1);

    const float Acoef = -__expf(A_log[d * NST + n]);
    const size_t base = (size_t)b * LEN + (size_t)c * CHL;

    float h = 0.f, ap = 1.f;
#pragma unroll 4
    for (int l = 0; l < CHL; l++) {
        size_t r = base + l;
        float dt = g_dt[r * DI + d];
        float u  = g_xconv[r * DI + d];
        float Bv = g_xdbl[r * XDBL_W + RRANK + n];
        float a = __expf(dt * Acoef);
        h = fmaf(a, h, dt * Bv * u);
        ap *= a;
    }
    const int idx = (gc * NST + n) * NCH + c;
    g_aprod[idx] = ap;
    g_hend[idx]  = h;
}

__global__ __launch_bounds__(256) void scan_pass2(
    const float* __restrict__ A_log,
    const float* __restrict__ D_param,
    float* __restrict__ h_final)
{
    const int tid = threadIdx.x;
    const int G  = blockIdx.x * 16 + (tid >> 4);
    const int c  = G & (NCH - 1);
    const int gc = G >> 4;
    const int n  = tid & 15;
    const int b  = gc >> 11;
    const int d  = gc & (DI - 1);

    const float Acoef = -__expf(A_log[d * NST + n]);
    const float Dv = D_param[d];
    const size_t base = (size_t)b * LEN + (size_t)c * CHL;

    // h at chunk start: fold summaries of chunks 0..c-1 in order.
    float h = 0.f;
    const int sbase = (gc * NST + n) * NCH;
    for (int cc = 0; cc < c; cc++)
        h = fmaf(g_aprod[sbase + cc], h, g_hend[sbase + cc]);

#pragma unroll 4
    for (int l = 0; l < CHL; l++) {
        size_t r = base + l;
        float dt = g_dt[r * DI + d];
        float u  = g_xconv[r * DI + d];
        float Bv = g_xdbl[r * XDBL_W + RRANK + n];
        float Cv = g_xdbl[r * XDBL_W + RRANK + NST + n];
        float a = __expf(dt * Acoef);
        h = fmaf(a, h, dt * Bv * u);
        float v = h * Cv;
#pragma unroll
        for (int off = 8; off; off >>= 1)
            v += __shfl_xor_sync(0xffffffffu, v, off);
        if (n == 0) {
            float zv = g_xz[r * (2 * DI) + DI + d];
            float sil = zv / (1.f + __expf(-zv));
            g_y[r * DI + d] = (v + Dv * u) * sil;
        }
    }
    if (c == NCH - 1)
        h_final[((size_t)b * DI + d) * NST + n] = h;
}

// ---------------- launch -----------------------------------------------------
extern "C" void kernel_launch(void* const* d_in, const int* in_sizes, int n_in,
                              void* d_out, int out_size)
{
    const float* x       = (const float*)d_in[0];
    const float* W_in    = (const float*)d_in[1];
    const float* conv_w  = (const float*)d_in[2];
    const float* conv_b  = (const float*)d_in[3];
    const float* W_x     = (const float*)d_in[4];
    const float* W_dt    = (const float*)d_in[5];
    const float* b_dt    = (const float*)d_in[6];
    const float* A_log   = (const float*)d_in[7];
    const float* D_param = (const float*)d_in[8];
    const float* W_out   = (const float*)d_in[9];

    float* out_f = (float*)d_out;
    float* out_main  = out_f;                                   // (2,1024,1024)
    float* out_hfin  = out_f + BATCH * LEN * DM;                // (2,2048,16)
    float* out_cache = out_hfin + BATCH * DI * NST;             // (2,2048,4)

    float *xz, *xdbl, *dt, *y;
    cudaGetSymbolAddress((void**)&xz, g_xz);
    cudaGetSymbolAddress((void**)&xdbl, g_xdbl);
    cudaGetSymbolAddress((void**)&dt, g_dt);
    cudaGetSymbolAddress((void**)&y, g_y);

    const int M = BATCH * LEN; // 2048

    // 1) xz = x @ W_in   (2048 x 4096 x 1024)  [fp16 TC]
    {
        dim3 grid((2 * DI) / TBN, M / TBM);
        fp16_gemm<0><<<grid, 256>>>(M, 2 * DI, DM, x, DM, W_in, 2 * DI,
                                    xz, 2 * DI, nullptr);
    }
    // 2) conv + silu
    {
        int tot = BATCH * LEN * DI;
        conv_silu_kernel<<<(tot + 255) / 256, 256>>>(conv_w, conv_b);
    }
    // 3) conv cache output
    {
        int tot = BATCH * DI * KCONV;
        conv_cache_kernel<<<(tot + 255) / 256, 256>>>(out_cache);
    }
    // 4) x_dbl = x_conv @ W_x   (2048 x 96 x 2048)  [split-K fp32]
    {
        dim3 grid(G2_KS, M / G2_BM);
        gemm2_partial<<<grid, 256>>>(W_x);
        int tot = BATCH * LEN * XDBL_W;
        xdbl_reduce_kernel<<<(tot + 255) / 256, 256>>>();
    }
    // 5) dt = softplus(dt_low @ W_dt + b_dt)   (2048 x 2048 x 64)  [fp16 TC]
    {
        dim3 grid(DI / TBN, M / TBM);
        fp16_gemm<1><<<grid, 256>>>(M, DI, RRANK, xdbl, XDBL_W, W_dt, DI,
                                    dt, DI, b_dt);
    }
    // 6) chunked parallel scan -> g_y, h_final
    {
        const int nblk = (BATCH * DI * NCH) / 16;   // 4096 blocks
        scan_pass1<<<nblk, 256>>>(A_log);
        scan_pass2<<<nblk, 256>>>(A_log, D_param, out_hfin);
    }
    // 7) out = y @ W_out   (2048 x 1024 x 2048)  [fp16 TC]
    {
        dim3 grid(DM / TBN, M / TBM);
        fp16_gemm<0><<<grid, 256>>>(M, DM, DI, y, DI, W_out, DM,
                                    out_main, DM, nullptr);
    }
}